// round 13
// baseline (speedup 1.0000x reference)
#include <cuda_runtime.h>
#include <cuda_fp16.h>
#include <math.h>
#include <stdint.h>

// ---------------------------------------------------------------------------
// Problem constants
// ---------------------------------------------------------------------------
constexpr int B_  = 4096;    // batch
constexpr int G_  = 1024;    // gate width
constexpr int KD  = 2048;    // IN + g  (GEMM K)
constexpr int ND  = 5120;    // out_dim
constexpr long long OUT_OH = (long long)B_ * 4 * G_;

// ---------------------------------------------------------------------------
// Static scratch (no allocations allowed)
// ---------------------------------------------------------------------------
__device__ __align__(256) __half g_A  [(size_t)B_ * KD];   // [input | h2_fl] 16.8 MB
__device__ __align__(256) __half g_Ah1[(size_t)B_ * G_];   // h1_fl (step-1 h half) 8.4 MB
__device__ __align__(256) __half g_W1[(size_t)ND * KD];    // 21 MB
__device__ __align__(256) __half g_W2[(size_t)ND * KD];    // 21 MB
__device__ double g_part[2 * 2048];

// ---------------------------------------------------------------------------
// PTX helpers (all baseline sm_80+ features)
// ---------------------------------------------------------------------------
__device__ __forceinline__ uint32_t smem_u32(const void* p) {
    uint32_t a;
    asm("{ .reg .u64 t; cvta.to.shared.u64 t, %1; cvt.u32.u64 %0, t; }" : "=r"(a) : "l"(p));
    return a;
}
__device__ __forceinline__ void cp_async16(uint32_t dst, const void* src) {
    asm volatile("cp.async.cg.shared.global [%0], [%1], 16;" :: "r"(dst), "l"(src) : "memory");
}
#define CP_COMMIT()  asm volatile("cp.async.commit_group;" ::: "memory")
#define CP_WAIT(n)   asm volatile("cp.async.wait_group %0;" :: "n"(n) : "memory")

#define LDSM4(r0, r1, r2, r3, addr) \
    asm volatile("ldmatrix.sync.aligned.m8n8.x4.shared.b16 {%0,%1,%2,%3}, [%4];" \
                 : "=r"(r0), "=r"(r1), "=r"(r2), "=r"(r3) : "r"(addr))

#define LDSM2(r0, r1, addr) \
    asm volatile("ldmatrix.sync.aligned.m8n8.x2.shared.b16 {%0,%1}, [%2];" \
                 : "=r"(r0), "=r"(r1) : "r"(addr))

#define MMA16816(d, a, b0v, b1v) \
    asm volatile("mma.sync.aligned.m16n8k16.row.col.f32.f16.f16.f32 " \
                 "{%0,%1,%2,%3}, {%4,%5,%6,%7}, {%8,%9}, {%0,%1,%2,%3};" \
                 : "+f"((d)[0]), "+f"((d)[1]), "+f"((d)[2]), "+f"((d)[3]) \
                 : "r"((a)[0]), "r"((a)[1]), "r"((a)[2]), "r"((a)[3]), \
                   "r"(b0v), "r"(b1v))

#define SWZ(o) ((o) ^ (((o) >> 3) & 0x70))

// Fast transcendentals: ex2/rcp/lg2 approx (rel err ~1e-7; safe vs fp16 GEMM err)
__device__ __forceinline__ float fsigm(float x) {
    float e, r;
    asm("ex2.approx.f32 %0, %1;" : "=f"(e) : "f"(-1.4426950408889634f * x));
    asm("rcp.approx.f32 %0, %1;" : "=f"(r) : "f"(1.0f + e));
    return r;
}
__device__ __forceinline__ float ftanh(float x) {
    return fmaf(2.0f, fsigm(2.0f * x), -1.0f);
}
__device__ __forceinline__ float flog2(float x) {
    float r;
    asm("lg2.approx.f32 %0, %1;" : "=f"(r) : "f"(x));
    return r;
}

// ---------------------------------------------------------------------------
// Pack A = fp16([input | h2_fl]) — 8 elements per thread, 16B stores
// ---------------------------------------------------------------------------
__global__ void prep_kernel(const float* __restrict__ inp,
                            const int*   __restrict__ hidden)
{
    const int g = blockIdx.x * 256 + threadIdx.x;  // 0 .. B_*KD/8-1
    const int idx = g * 8;
    const int i = idx >> 11;
    const int k = idx & 2047;                      // multiple of 8; no boundary straddle
    __half h[8];
    if (k < 1024) {
        const float4 f0 = *(const float4*)(inp + (size_t)i * 1024 + k);
        const float4 f1 = *(const float4*)(inp + (size_t)i * 1024 + k + 4);
        h[0]=__float2half_rn(f0.x); h[1]=__float2half_rn(f0.y);
        h[2]=__float2half_rn(f0.z); h[3]=__float2half_rn(f0.w);
        h[4]=__float2half_rn(f1.x); h[5]=__float2half_rn(f1.y);
        h[6]=__float2half_rn(f1.z); h[7]=__float2half_rn(f1.w);
    } else {
        const int4 v0 = *(const int4*)(hidden + (size_t)i * 4096 + k);
        const int4 v1 = *(const int4*)(hidden + (size_t)i * 4096 + k + 4);
        const float s = 1.0f / 8388608.0f;
        h[0]=__float2half_rn((float)v0.x*s); h[1]=__float2half_rn((float)v0.y*s);
        h[2]=__float2half_rn((float)v0.z*s); h[3]=__float2half_rn((float)v0.w*s);
        h[4]=__float2half_rn((float)v1.x*s); h[5]=__float2half_rn((float)v1.y*s);
        h[6]=__float2half_rn((float)v1.z*s); h[7]=__float2half_rn((float)v1.w*s);
    }
    *(uint4*)(g_A + idx) = *(const uint4*)h;
}

// ---------------------------------------------------------------------------
// W1,W2 -> fp16, 8 elements per thread
// ---------------------------------------------------------------------------
__global__ void wconv_kernel(const float* __restrict__ W1src,
                             const float* __restrict__ W2src)
{
    constexpr size_t HALF = (size_t)ND * KD;
    const size_t idx = ((size_t)blockIdx.x * 256 + threadIdx.x) * 8;
    const float* src = (idx < HALF) ? (W1src + idx) : (W2src + (idx - HALF));
    __half* dst = (idx < HALF) ? (g_W1 + idx) : (g_W2 + (idx - HALF));
    const float4 f0 = *(const float4*)(src);
    const float4 f1 = *(const float4*)(src + 4);
    __half h[8];
    h[0]=__float2half_rn(f0.x); h[1]=__float2half_rn(f0.y);
    h[2]=__float2half_rn(f0.z); h[3]=__float2half_rn(f0.w);
    h[4]=__float2half_rn(f1.x); h[5]=__float2half_rn(f1.y);
    h[6]=__float2half_rn(f1.z); h[7]=__float2half_rn(f1.w);
    *(uint4*)dst = *(const uint4*)h;
}

// ---------------------------------------------------------------------------
// Fused GEMM + fixed-point half-step.
// CTA: M=64 batch rows x 32 j-columns x ALL 5 gates (B tile = 160 W rows).
// Grid 2048 CTAs (vs 1024) -> ~6.9 waves, killing the 3.46-wave ceil loss.
// 8 warps: wm = (wid&1)*32, j-slice wjj = (wid>>1)*8. Warp tile 32(M)x8(j)x5.
// B: 5 gate blocks, one LDSM2 each per k16 slice.
// K-chunk 64, SW128 swizzle, 3-stage cp.async, one barrier per chunk.
// Step-1 h-half read from disjoint g_Ah1 (no cross-CTA WAR).
// ---------------------------------------------------------------------------
constexpr int TMM = 64;
constexpr int A_BYTES = TMM * 128;                 // 8192 per stage
constexpr int B_BYTES = 160 * 128;                 // 20480 per stage
constexpr int STAGE_BYTES = A_BYTES + B_BYTES;     // 28672
constexpr int SMEM_TOTAL = 3 * STAGE_BYTES;        // 86016
constexpr int NCHUNK = KD / 64;                    // 32

__global__ __launch_bounds__(256, 2)
void gemm_fused_kernel(int step, const float* __restrict__ bias,
                       const int* __restrict__ hidden,
                       float* __restrict__ out)
{
    extern __shared__ char smem[];
    __shared__ double sred[256];
    const uint32_t sb = smem_u32(smem);
    const int tid  = threadIdx.x;
    const int wid  = tid >> 5;
    const int lane = tid & 31;
    const int bm  = blockIdx.y * TMM;
    const int bj0 = blockIdx.x * 32;
    const __half* __restrict__ Wg = step ? g_W2 : g_W1;

    // ---- producer setup: 2 A + 5 B cp.async per thread per stage ----
    const int prow = tid >> 3;                     // 0..31
    const int pgrp = tid & 7;                      // 0..7
    const char* Abase  = (const char*)(g_A   + (size_t)(bm + prow) * KD) + pgrp * 16;
    const char* Hbase  = (const char*)(g_Ah1 + (size_t)(bm + prow) * G_) + pgrp * 16;
    const char* Bbase  = (const char*)(Wg + (size_t)(bj0 + prow) * KD) + pgrp * 16;
    const uint32_t dA = SWZ((uint32_t)(prow * 128 + pgrp * 16));   // row step 32 is SWZ-safe
    constexpr size_t ASTRIDE = (size_t)32 * KD * 2;                // +32 rows in g_A
    constexpr size_t HSTRIDE = (size_t)32 * G_ * 2;                // +32 rows in g_Ah1
    constexpr size_t BSTRIDE = (size_t)1024 * KD * 2;              // next gate
    const bool useH = (step != 0);

    // ---- consumer setup ----
    const int wm  = (wid & 1) * 32;                // warp M offset
    const int wjj = (wid >> 1) * 8;                // warp j-slice
    const int q   = lane >> 3;                     // quad
    const int l7  = lane & 7;

    uint32_t a_rt[2], a_xor[2];
#pragma unroll
    for (int mt = 0; mt < 2; mt++) {
        const int row = wm + mt * 16 + l7 + (q & 1) * 8;
        a_rt[mt]  = (uint32_t)row * 128;
        a_xor[mt] = (uint32_t)(row & 7) * 16;
    }
    const uint32_t a_kh = (uint32_t)(q >> 1) * 16;

    // B: 5 gate blocks of 8 rows each; ldmatrix.x2 (lanes 0-15 give addresses)
    uint32_t b_rt[5];
#pragma unroll
    for (int gt = 0; gt < 5; gt++)
        b_rt[gt] = (uint32_t)(A_BYTES + (gt * 32 + wjj + l7) * 128);
    const uint32_t b_xor = (uint32_t)l7 * 16;
    const uint32_t b_kh  = (uint32_t)(q & 1) * 16;

    float acc[2][5][4];
#pragma unroll
    for (int mt = 0; mt < 2; mt++)
#pragma unroll
        for (int gt = 0; gt < 5; gt++)
#pragma unroll
            for (int r = 0; r < 4; r++) acc[mt][gt][r] = 0.0f;

    // ---- prologue: chunks 0,1 into stages 0,1 (low chunks -> g_A) ----
#pragma unroll
    for (int s = 0; s < 2; s++) {
        const uint32_t sdst = sb + s * STAGE_BYTES;
        const size_t koff = (size_t)s * 128;
#pragma unroll
        for (int i = 0; i < 2; i++)
            cp_async16(sdst + dA + i * 4096, Abase + i * ASTRIDE + koff);
#pragma unroll
        for (int j = 0; j < 5; j++)
            cp_async16(sdst + A_BYTES + dA + j * 4096, Bbase + j * BSTRIDE + koff);
        CP_COMMIT();
    }

    // ---- main loop: one barrier per chunk ----
    int sc = 0, sl = 2;
    for (int c = 0; c < NCHUNK; c++) {
        CP_WAIT(1);
        __syncthreads();
        if (c + 2 < NCHUNK) {
            const uint32_t sdst = sb + sl * STAGE_BYTES;
            const int cl = c + 2;
            if (useH && cl >= 16) {                 // h half from g_Ah1
                const size_t koff = (size_t)(cl - 16) * 128;
#pragma unroll
                for (int i = 0; i < 2; i++)
                    cp_async16(sdst + dA + i * 4096, Hbase + i * HSTRIDE + koff);
            } else {                                // input half / step-0 h2 from g_A
                const size_t koff = (size_t)cl * 128;
#pragma unroll
                for (int i = 0; i < 2; i++)
                    cp_async16(sdst + dA + i * 4096, Abase + i * ASTRIDE + koff);
            }
            const size_t koffB = (size_t)cl * 128;
#pragma unroll
            for (int j = 0; j < 5; j++)
                cp_async16(sdst + A_BYTES + dA + j * 4096, Bbase + j * BSTRIDE + koffB);
        }
        CP_COMMIT();

        const uint32_t sA = sb + sc * STAGE_BYTES;
#pragma unroll
        for (int kk = 0; kk < 4; kk++) {
            const uint32_t kb = kk * 32;
            const uint32_t bko = (kb + b_kh) ^ b_xor;   // folded once per kk
            uint32_t af[2][4];
#pragma unroll
            for (int mt = 0; mt < 2; mt++)
                LDSM4(af[mt][0], af[mt][1], af[mt][2], af[mt][3],
                      sA + a_rt[mt] + ((kb + a_kh) ^ a_xor[mt]));
            uint32_t bf[5][2];
#pragma unroll
            for (int gt = 0; gt < 5; gt++)
                LDSM2(bf[gt][0], bf[gt][1], sA + b_rt[gt] + bko);
#pragma unroll
            for (int mt = 0; mt < 2; mt++)
#pragma unroll
                for (int gt = 0; gt < 5; gt++)
                    MMA16816(acc[mt][gt], af[mt], bf[gt][0], bf[gt][1]);
        }

        sc = (sc == 2) ? 0 : sc + 1;
        sl = (sl == 2) ? 0 : sl + 1;
    }

    // ---- fused elementwise epilogue (all 5 gates resident in registers) ----
    const int trow = lane >> 2;
    const int tcol = (lane & 3) * 2;
    const int jb   = bj0 + wjj + tcol;             // global j for cc=0

    float bz[5][2];
#pragma unroll
    for (int gt = 0; gt < 5; gt++) {
        bz[gt][0] = __ldg(bias + gt * 1024 + jb);
        bz[gt][1] = __ldg(bias + gt * 1024 + jb + 1);
    }

    double lsum = 0.0;
#pragma unroll
    for (int mt = 0; mt < 2; mt++) {
#pragma unroll
        for (int r2 = 0; r2 < 2; r2++) {
            const int i = bm + wm + mt * 16 + trow + r2 * 8;
            const int* hrow = hidden + (size_t)i * 4096;
            const size_t ro = (size_t)i * 4096;
            const size_t oo = OUT_OH + (size_t)i * 2048 + (size_t)step * 1024;
#pragma unroll
            for (int cc = 0; cc < 2; cc++) {
                const int j = jb + cc;
                const int a = r2 * 2 + cc;
                const float xz = acc[mt][0][a] + bz[0][cc];
                const float xg = acc[mt][1][a] + bz[1][cc];
                const float xf = acc[mt][2][a] + bz[2][cc];
                const float xo = acc[mt][3][a] + bz[3][cc];
                const float xp = acc[mt][4][a] + bz[4][cc];

                const float z  = 0.96875f * fsigm(xz) + 0.03125f;
                const float gg = ftanh(xg);
                const float f  = fsigm(xf);
                const float o  = fsigm(xo);
                const float p  = 0.96875f * fsigm(xp) + 0.03125f;

                int zi = (int)(z * 1024.0f); if (zi < 1) zi = 1;
                int pi = (int)(p * 1024.0f); if (pi < 1) pi = 1;

                const int cv = hrow[(2 + step) * 1024 + j];
                const int hv = hrow[step * 1024 + j];

                const int cn = (int)(((long long)cv * (long long)zi) >> 10)
                             + (int)(f * gg * 8388608.0f);
                const float cfl = (float)cn * (1.0f / 8388608.0f);
                const int hn = (int)(((long long)hv * (long long)pi) >> 10)
                             + (int)(o * ftanh(cfl) * 8388608.0f);

                out[ro + (size_t)step * 1024 + j]       = (float)hn;
                out[ro + (size_t)(2 + step) * 1024 + j] = (float)cn;
                const float hfl = (float)hn * (1.0f / 8388608.0f);
                out[oo + j] = hfl;
                if (step == 0)
                    g_Ah1[(size_t)i * G_ + j] = __float2half_rn(hfl);

                lsum += (double)flog2(z * p);      // sum of log2 directly
            }
        }
    }

    // ---- deterministic per-CTA log2 reduction ----
    sred[tid] = lsum;
    __syncthreads();
#pragma unroll
    for (int s = 128; s > 0; s >>= 1) {
        if (tid < s) sred[tid] += sred[tid + s];
        __syncthreads();
    }
    if (tid == 0)
        g_part[step * 2048 + blockIdx.y * gridDim.x + blockIdx.x] = sred[0];
}

// ---------------------------------------------------------------------------
// Final scalar: optimal_bits = -(sum of log2)
// ---------------------------------------------------------------------------
__global__ void bits_kernel(float* __restrict__ out, long long last_idx)
{
    __shared__ double sred[256];
    const int tid = threadIdx.x;
    double s = 0.0;
    for (int i = tid; i < 2 * 2048; i += 256) s += g_part[i];
    sred[tid] = s;
    __syncthreads();
#pragma unroll
    for (int k = 128; k > 0; k >>= 1) {
        if (tid < k) sred[tid] += sred[tid + k];
        __syncthreads();
    }
    if (tid == 0)
        out[last_idx] = (float)(-sred[0]);
}

// ---------------------------------------------------------------------------
extern "C" void kernel_launch(void* const* d_in, const int* in_sizes, int n_in,
                              void* d_out, int out_size)
{
    const float* inp    = (const float*)d_in[0];   // (4096, 1024)
    const int*   hidden = (const int*)  d_in[1];   // (4096, 4096)
    const float* W1     = (const float*)d_in[2];   // (5120, 2048)
    const float* b1     = (const float*)d_in[3];
    const float* W2     = (const float*)d_in[4];
    const float* b2     = (const float*)d_in[5];
    float* out = (float*)d_out;

    static bool attr_set = false;
    if (!attr_set) {
        cudaFuncSetAttribute(gemm_fused_kernel,
                             cudaFuncAttributeMaxDynamicSharedMemorySize, SMEM_TOTAL);
        attr_set = true;
    }

    dim3 gemm_grid(G_ / 32, B_ / TMM);             // (32, 64) = 2048 CTAs

    prep_kernel <<<(B_ * KD) / (256 * 8), 256>>>(inp, hidden);
    wconv_kernel<<<(2 * ND * KD) / (256 * 8), 256>>>(W1, W2);

    gemm_fused_kernel<<<gemm_grid, 256, SMEM_TOTAL>>>(0, b1, hidden, out);
    gemm_fused_kernel<<<gemm_grid, 256, SMEM_TOTAL>>>(1, b2, hidden, out);
    bits_kernel<<<1, 256>>>(out, (long long)out_size - 1);
}

// round 14
// speedup vs baseline: 1.1602x; 1.1602x over previous
#include <cuda_runtime.h>
#include <cuda_fp16.h>
#include <math.h>
#include <stdint.h>

// ---------------------------------------------------------------------------
// Problem constants
// ---------------------------------------------------------------------------
constexpr int B_  = 4096;    // batch
constexpr int G_  = 1024;    // gate width
constexpr int KD  = 2048;    // IN + g  (GEMM K)
constexpr int ND  = 5120;    // out_dim
constexpr long long OUT_OH = (long long)B_ * 4 * G_;

// ---------------------------------------------------------------------------
// Static scratch (no allocations allowed)
// ---------------------------------------------------------------------------
__device__ __align__(256) __half g_A  [(size_t)B_ * KD];   // [input | h2_fl] 16.8 MB
__device__ __align__(256) __half g_Ah1[(size_t)B_ * G_];   // h1_fl (step-1 h half) 8.4 MB
__device__ __align__(256) __half g_W1[(size_t)ND * KD];    // 21 MB
__device__ __align__(256) __half g_W2[(size_t)ND * KD];    // 21 MB
__device__ double g_part[2 * 1024];
__device__ int    g_done[32];                               // per-m-block h1-ready counters

// ---------------------------------------------------------------------------
// PTX helpers (all baseline sm_80+ features)
// ---------------------------------------------------------------------------
__device__ __forceinline__ uint32_t smem_u32(const void* p) {
    uint32_t a;
    asm("{ .reg .u64 t; cvta.to.shared.u64 t, %1; cvt.u32.u64 %0, t; }" : "=r"(a) : "l"(p));
    return a;
}
__device__ __forceinline__ void cp_async16(uint32_t dst, const void* src) {
    asm volatile("cp.async.cg.shared.global [%0], [%1], 16;" :: "r"(dst), "l"(src) : "memory");
}
#define CP_COMMIT()  asm volatile("cp.async.commit_group;" ::: "memory")
#define CP_WAIT(n)   asm volatile("cp.async.wait_group %0;" :: "n"(n) : "memory")

#define LDSM4(r0, r1, r2, r3, addr) \
    asm volatile("ldmatrix.sync.aligned.m8n8.x4.shared.b16 {%0,%1,%2,%3}, [%4];" \
                 : "=r"(r0), "=r"(r1), "=r"(r2), "=r"(r3) : "r"(addr))

#define LDSM2(r0, r1, addr) \
    asm volatile("ldmatrix.sync.aligned.m8n8.x2.shared.b16 {%0,%1}, [%2];" \
                 : "=r"(r0), "=r"(r1) : "r"(addr))

#define MMA16816(d, a, b0v, b1v) \
    asm volatile("mma.sync.aligned.m16n8k16.row.col.f32.f16.f16.f32 " \
                 "{%0,%1,%2,%3}, {%4,%5,%6,%7}, {%8,%9}, {%0,%1,%2,%3};" \
                 : "+f"((d)[0]), "+f"((d)[1]), "+f"((d)[2]), "+f"((d)[3]) \
                 : "r"((a)[0]), "r"((a)[1]), "r"((a)[2]), "r"((a)[3]), \
                   "r"(b0v), "r"(b1v))

#define SWZ(o) ((o) ^ (((o) >> 3) & 0x70))

// Fast transcendentals: ex2/rcp/lg2 approx (rel err ~1e-7; safe vs fp16 GEMM err)
__device__ __forceinline__ float fsigm(float x) {
    float e, r;
    asm("ex2.approx.f32 %0, %1;" : "=f"(e) : "f"(-1.4426950408889634f * x));
    asm("rcp.approx.f32 %0, %1;" : "=f"(r) : "f"(1.0f + e));
    return r;
}
__device__ __forceinline__ float ftanh(float x) {
    return fmaf(2.0f, fsigm(2.0f * x), -1.0f);
}
__device__ __forceinline__ float flog2(float x) {
    float r;
    asm("lg2.approx.f32 %0, %1;" : "=f"(r) : "f"(x));
    return r;
}

// ---------------------------------------------------------------------------
// Pack A = fp16([input | h2_fl]) — 8 elements per thread; also zero g_done
// ---------------------------------------------------------------------------
__global__ void prep_kernel(const float* __restrict__ inp,
                            const int*   __restrict__ hidden)
{
    if (blockIdx.x == 0 && threadIdx.x < 32) g_done[threadIdx.x] = 0;
    const int g = blockIdx.x * 256 + threadIdx.x;  // 0 .. B_*KD/8-1
    const int idx = g * 8;
    const int i = idx >> 11;
    const int k = idx & 2047;                      // multiple of 8; no boundary straddle
    __half h[8];
    if (k < 1024) {
        const float4 f0 = *(const float4*)(inp + (size_t)i * 1024 + k);
        const float4 f1 = *(const float4*)(inp + (size_t)i * 1024 + k + 4);
        h[0]=__float2half_rn(f0.x); h[1]=__float2half_rn(f0.y);
        h[2]=__float2half_rn(f0.z); h[3]=__float2half_rn(f0.w);
        h[4]=__float2half_rn(f1.x); h[5]=__float2half_rn(f1.y);
        h[6]=__float2half_rn(f1.z); h[7]=__float2half_rn(f1.w);
    } else {
        const int4 v0 = *(const int4*)(hidden + (size_t)i * 4096 + k);
        const int4 v1 = *(const int4*)(hidden + (size_t)i * 4096 + k + 4);
        const float s = 1.0f / 8388608.0f;
        h[0]=__float2half_rn((float)v0.x*s); h[1]=__float2half_rn((float)v0.y*s);
        h[2]=__float2half_rn((float)v0.z*s); h[3]=__float2half_rn((float)v0.w*s);
        h[4]=__float2half_rn((float)v1.x*s); h[5]=__float2half_rn((float)v1.y*s);
        h[6]=__float2half_rn((float)v1.z*s); h[7]=__float2half_rn((float)v1.w*s);
    }
    *(uint4*)(g_A + idx) = *(const uint4*)h;
}

// ---------------------------------------------------------------------------
// W1,W2 -> fp16, 8 elements per thread
// ---------------------------------------------------------------------------
__global__ void wconv_kernel(const float* __restrict__ W1src,
                             const float* __restrict__ W2src)
{
    constexpr size_t HALF = (size_t)ND * KD;
    const size_t idx = ((size_t)blockIdx.x * 256 + threadIdx.x) * 8;
    const float* src = (idx < HALF) ? (W1src + idx) : (W2src + (idx - HALF));
    __half* dst = (idx < HALF) ? (g_W1 + idx) : (g_W2 + (idx - HALF));
    const float4 f0 = *(const float4*)(src);
    const float4 f1 = *(const float4*)(src + 4);
    __half h[8];
    h[0]=__float2half_rn(f0.x); h[1]=__float2half_rn(f0.y);
    h[2]=__float2half_rn(f0.z); h[3]=__float2half_rn(f0.w);
    h[4]=__float2half_rn(f1.x); h[5]=__float2half_rn(f1.y);
    h[6]=__float2half_rn(f1.z); h[7]=__float2half_rn(f1.w);
    *(uint4*)dst = *(const uint4*)h;
}

// ---------------------------------------------------------------------------
// MERGED fused GEMM + fixed-point half-step for BOTH steps in one launch.
// bid < 1024: step 0;  bid >= 1024: step 1 (same tile config as R12 best).
// CTA: M=128 x 32 j-columns x 5 gates. 8 warps: wm=(wid&1)*64, wjj=(wid>>1)*8.
// K-chunk 64, SW128, 3-stage cp.async, one barrier per chunk.
// Step-1 chunks 0-15 are input-half (no dependency) -> computed immediately,
// overlapping step-0's tail wave. Before issuing chunk 16 (h1 half from
// g_Ah1), spin on g_done[bm/128] == 32 (released by step-0 CTAs after
// threadfence'd h1 stores). Block dispatch is bid-ordered -> no deadlock.
// ---------------------------------------------------------------------------
constexpr int TMM = 128;
constexpr int A_BYTES = TMM * 128;                 // 16384 per stage
constexpr int B_BYTES = 160 * 128;                 // 20480 per stage
constexpr int STAGE_BYTES = A_BYTES + B_BYTES;     // 36864
constexpr int SMEM_TOTAL = 3 * STAGE_BYTES;        // 110592
constexpr int NCHUNK = KD / 64;                    // 32

__global__ __launch_bounds__(256, 2)
void gemm_fused_kernel(const float* __restrict__ bias1,
                       const float* __restrict__ bias2,
                       const int* __restrict__ hidden,
                       float* __restrict__ out)
{
    extern __shared__ char smem[];
    __shared__ double sred[256];
    const uint32_t sb = smem_u32(smem);
    const int tid  = threadIdx.x;
    const int wid  = tid >> 5;
    const int lane = tid & 31;
    const int bid  = blockIdx.x;
    const int step = bid >> 10;                    // 0 or 1
    const int r    = bid & 1023;
    const int bj0  = (r & 31) * 32;
    const int bm   = (r >> 5) * TMM;
    const float* __restrict__ bias = step ? bias2 : bias1;
    const __half* __restrict__ Wg  = step ? g_W2 : g_W1;

    // ---- producer setup: 4 A + 5 B cp.async per thread per stage ----
    const int prow = tid >> 3;                     // 0..31
    const int pgrp = tid & 7;                      // 0..7
    const char* Abase  = (const char*)(g_A   + (size_t)(bm + prow) * KD) + pgrp * 16;
    const char* Hbase  = (const char*)(g_Ah1 + (size_t)(bm + prow) * G_) + pgrp * 16;
    const char* Bbase  = (const char*)(Wg + (size_t)(bj0 + prow) * KD) + pgrp * 16;
    const uint32_t dA = SWZ((uint32_t)(prow * 128 + pgrp * 16));   // row step 32 is SWZ-safe
    constexpr size_t ASTRIDE = (size_t)32 * KD * 2;                // +32 rows in g_A
    constexpr size_t HSTRIDE = (size_t)32 * G_ * 2;                // +32 rows in g_Ah1
    constexpr size_t BSTRIDE = (size_t)1024 * KD * 2;              // next gate
    const bool useH = (step != 0);

    // ---- consumer setup ----
    const int wm  = (wid & 1) * 64;                // warp M offset
    const int wjj = (wid >> 1) * 8;                // warp j-slice
    const int q   = lane >> 3;                     // quad
    const int l7  = lane & 7;

    uint32_t a_rt[4], a_xor[4];
#pragma unroll
    for (int mt = 0; mt < 4; mt++) {
        const int row = wm + mt * 16 + l7 + (q & 1) * 8;
        a_rt[mt]  = (uint32_t)row * 128;
        a_xor[mt] = (uint32_t)(row & 7) * 16;
    }
    const uint32_t a_kh = (uint32_t)(q >> 1) * 16;

    uint32_t b_rt[5];
#pragma unroll
    for (int gt = 0; gt < 5; gt++)
        b_rt[gt] = (uint32_t)(A_BYTES + (gt * 32 + wjj + l7) * 128);
    const uint32_t b_xor = (uint32_t)l7 * 16;
    const uint32_t b_kh  = (uint32_t)(q & 1) * 16;

    float acc[4][5][4];
#pragma unroll
    for (int mt = 0; mt < 4; mt++)
#pragma unroll
        for (int gt = 0; gt < 5; gt++)
#pragma unroll
            for (int rr = 0; rr < 4; rr++) acc[mt][gt][rr] = 0.0f;

    // ---- prologue: chunks 0,1 (input half -> g_A; no dependency) ----
#pragma unroll
    for (int s = 0; s < 2; s++) {
        const uint32_t sdst = sb + s * STAGE_BYTES;
        const size_t koff = (size_t)s * 128;
#pragma unroll
        for (int i = 0; i < 4; i++)
            cp_async16(sdst + dA + i * 4096, Abase + i * ASTRIDE + koff);
#pragma unroll
        for (int j = 0; j < 5; j++)
            cp_async16(sdst + A_BYTES + dA + j * 4096, Bbase + j * BSTRIDE + koff);
        CP_COMMIT();
    }

    // ---- main loop: one barrier per chunk ----
    int sc = 0, sl = 2;
    for (int c = 0; c < NCHUNK; c++) {
        CP_WAIT(1);
        __syncthreads();

        // Before issuing chunk 16 (first h1 chunk), step-1 waits for all 32
        // step-0 CTAs covering this m-block to have published h1.
        if (useH && c == 14) {
            if (tid == 0) {
                while (atomicAdd(&g_done[bm >> 7], 0) < 32) __nanosleep(200);
            }
            __syncthreads();
            __threadfence();
        }

        if (c + 2 < NCHUNK) {
            const uint32_t sdst = sb + sl * STAGE_BYTES;
            const int cl = c + 2;
            if (useH && cl >= 16) {                 // h half from g_Ah1
                const size_t koff = (size_t)(cl - 16) * 128;
#pragma unroll
                for (int i = 0; i < 4; i++)
                    cp_async16(sdst + dA + i * 4096, Hbase + i * HSTRIDE + koff);
            } else {                                // input half / step-0 h2 from g_A
                const size_t koff = (size_t)cl * 128;
#pragma unroll
                for (int i = 0; i < 4; i++)
                    cp_async16(sdst + dA + i * 4096, Abase + i * ASTRIDE + koff);
            }
            const size_t koffB = (size_t)cl * 128;
#pragma unroll
            for (int j = 0; j < 5; j++)
                cp_async16(sdst + A_BYTES + dA + j * 4096, Bbase + j * BSTRIDE + koffB);
        }
        CP_COMMIT();

        const uint32_t sA = sb + sc * STAGE_BYTES;
#pragma unroll
        for (int kk = 0; kk < 4; kk++) {
            const uint32_t kb = kk * 32;
            const uint32_t bko = (kb + b_kh) ^ b_xor;   // folded once per kk
            uint32_t af[4][4];
#pragma unroll
            for (int mt = 0; mt < 4; mt++)
                LDSM4(af[mt][0], af[mt][1], af[mt][2], af[mt][3],
                      sA + a_rt[mt] + ((kb + a_kh) ^ a_xor[mt]));
            uint32_t bf[5][2];
#pragma unroll
            for (int gt = 0; gt < 5; gt++)
                LDSM2(bf[gt][0], bf[gt][1], sA + b_rt[gt] + bko);
#pragma unroll
            for (int mt = 0; mt < 4; mt++)
#pragma unroll
                for (int gt = 0; gt < 5; gt++)
                    MMA16816(acc[mt][gt], af[mt], bf[gt][0], bf[gt][1]);
        }

        sc = (sc == 2) ? 0 : sc + 1;
        sl = (sl == 2) ? 0 : sl + 1;
    }

    // ---- fused elementwise epilogue (all 5 gates resident in registers) ----
    const int trow = lane >> 2;
    const int tcol = (lane & 3) * 2;
    const int jb   = bj0 + wjj + tcol;             // global j for cc=0

    float bz[5][2];
#pragma unroll
    for (int gt = 0; gt < 5; gt++) {
        bz[gt][0] = __ldg(bias + gt * 1024 + jb);
        bz[gt][1] = __ldg(bias + gt * 1024 + jb + 1);
    }

    double lsum = 0.0;
#pragma unroll
    for (int mt = 0; mt < 4; mt++) {
#pragma unroll
        for (int r2 = 0; r2 < 2; r2++) {
            const int i = bm + wm + mt * 16 + trow + r2 * 8;
            const int* hrow = hidden + (size_t)i * 4096;
            const size_t ro = (size_t)i * 4096;
            const size_t oo = OUT_OH + (size_t)i * 2048 + (size_t)step * 1024;
#pragma unroll
            for (int cc = 0; cc < 2; cc++) {
                const int j = jb + cc;
                const int a = r2 * 2 + cc;
                const float xz = acc[mt][0][a] + bz[0][cc];
                const float xg = acc[mt][1][a] + bz[1][cc];
                const float xf = acc[mt][2][a] + bz[2][cc];
                const float xo = acc[mt][3][a] + bz[3][cc];
                const float xp = acc[mt][4][a] + bz[4][cc];

                const float z  = 0.96875f * fsigm(xz) + 0.03125f;
                const float gg = ftanh(xg);
                const float f  = fsigm(xf);
                const float o  = fsigm(xo);
                const float p  = 0.96875f * fsigm(xp) + 0.03125f;

                int zi = (int)(z * 1024.0f); if (zi < 1) zi = 1;
                int pi = (int)(p * 1024.0f); if (pi < 1) pi = 1;

                const int cv = hrow[(2 + step) * 1024 + j];
                const int hv = hrow[step * 1024 + j];

                const int cn = (int)(((long long)cv * (long long)zi) >> 10)
                             + (int)(f * gg * 8388608.0f);
                const float cfl = (float)cn * (1.0f / 8388608.0f);
                const int hn = (int)(((long long)hv * (long long)pi) >> 10)
                             + (int)(o * ftanh(cfl) * 8388608.0f);

                out[ro + (size_t)step * 1024 + j]       = (float)hn;
                out[ro + (size_t)(2 + step) * 1024 + j] = (float)cn;
                const float hfl = (float)hn * (1.0f / 8388608.0f);
                out[oo + j] = hfl;
                if (step == 0)
                    g_Ah1[(size_t)i * G_ + j] = __float2half_rn(hfl);

                lsum += (double)flog2(z * p);      // sum of log2 directly
            }
        }
    }

    // Publish h1 for step 1: every thread fences its own stores, barrier,
    // then one thread bumps the per-m-block counter.
    if (step == 0) __threadfence();

    // ---- deterministic per-CTA log2 reduction ----
    sred[tid] = lsum;
    __syncthreads();
#pragma unroll
    for (int s = 128; s > 0; s >>= 1) {
        if (tid < s) sred[tid] += sred[tid + s];
        __syncthreads();
    }
    if (tid == 0) {
        g_part[step * 1024 + r] = sred[0];
        if (step == 0) atomicAdd(&g_done[bm >> 7], 1);
    }
}

// ---------------------------------------------------------------------------
// Final scalar: optimal_bits = -(sum of log2)
// ---------------------------------------------------------------------------
__global__ void bits_kernel(float* __restrict__ out, long long last_idx)
{
    __shared__ double sred[256];
    const int tid = threadIdx.x;
    double s = 0.0;
    for (int i = tid; i < 2 * 1024; i += 256) s += g_part[i];
    sred[tid] = s;
    __syncthreads();
#pragma unroll
    for (int k = 128; k > 0; k >>= 1) {
        if (tid < k) sred[tid] += sred[tid + k];
        __syncthreads();
    }
    if (tid == 0)
        out[last_idx] = (float)(-sred[0]);
}

// ---------------------------------------------------------------------------
extern "C" void kernel_launch(void* const* d_in, const int* in_sizes, int n_in,
                              void* d_out, int out_size)
{
    const float* inp    = (const float*)d_in[0];   // (4096, 1024)
    const int*   hidden = (const int*)  d_in[1];   // (4096, 4096)
    const float* W1     = (const float*)d_in[2];   // (5120, 2048)
    const float* b1     = (const float*)d_in[3];
    const float* W2     = (const float*)d_in[4];
    const float* b2     = (const float*)d_in[5];
    float* out = (float*)d_out;

    static bool attr_set = false;
    if (!attr_set) {
        cudaFuncSetAttribute(gemm_fused_kernel,
                             cudaFuncAttributeMaxDynamicSharedMemorySize, SMEM_TOTAL);
        attr_set = true;
    }

    prep_kernel <<<(B_ * KD) / (256 * 8), 256>>>(inp, hidden);
    wconv_kernel<<<(2 * ND * KD) / (256 * 8), 256>>>(W1, W2);

    gemm_fused_kernel<<<2048, 256, SMEM_TOTAL>>>(b1, b2, hidden, out);
    bits_kernel<<<1, 256>>>(out, (long long)out_size - 1);
}

// round 15
// speedup vs baseline: 1.1692x; 1.0078x over previous
#include <cuda_runtime.h>
#include <cuda_fp16.h>
#include <math.h>
#include <stdint.h>

// ---------------------------------------------------------------------------
// Problem constants
// ---------------------------------------------------------------------------
constexpr int B_  = 4096;    // batch
constexpr int G_  = 1024;    // gate width
constexpr int KD  = 2048;    // IN + g  (GEMM K)
constexpr int ND  = 5120;    // out_dim
constexpr long long OUT_OH = (long long)B_ * 4 * G_;

// ---------------------------------------------------------------------------
// Static scratch (no allocations allowed)
// ---------------------------------------------------------------------------
__device__ __align__(256) __half g_A  [(size_t)B_ * KD];   // [input | h2_fl] 16.8 MB
__device__ __align__(256) __half g_Ah1[(size_t)B_ * G_];   // h1_fl (step-1 h half) 8.4 MB
__device__ __align__(256) __half g_W1[(size_t)ND * KD];    // 21 MB
__device__ __align__(256) __half g_W2[(size_t)ND * KD];    // 21 MB
__device__ double g_part[2 * 1024];
__device__ int    g_done[32];                               // per-m-block h1-ready counters

// ---------------------------------------------------------------------------
// PTX helpers (all baseline sm_80+ features)
// ---------------------------------------------------------------------------
__device__ __forceinline__ uint32_t smem_u32(const void* p) {
    uint32_t a;
    asm("{ .reg .u64 t; cvta.to.shared.u64 t, %1; cvt.u32.u64 %0, t; }" : "=r"(a) : "l"(p));
    return a;
}
__device__ __forceinline__ void cp_async16(uint32_t dst, const void* src) {
    asm volatile("cp.async.cg.shared.global [%0], [%1], 16;" :: "r"(dst), "l"(src) : "memory");
}
#define CP_COMMIT()  asm volatile("cp.async.commit_group;" ::: "memory")
#define CP_WAIT(n)   asm volatile("cp.async.wait_group %0;" :: "n"(n) : "memory")

#define LDSM4(r0, r1, r2, r3, addr) \
    asm volatile("ldmatrix.sync.aligned.m8n8.x4.shared.b16 {%0,%1,%2,%3}, [%4];" \
                 : "=r"(r0), "=r"(r1), "=r"(r2), "=r"(r3) : "r"(addr))

#define LDSM2(r0, r1, addr) \
    asm volatile("ldmatrix.sync.aligned.m8n8.x2.shared.b16 {%0,%1}, [%2];" \
                 : "=r"(r0), "=r"(r1) : "r"(addr))

#define MMA16816(d, a, b0v, b1v) \
    asm volatile("mma.sync.aligned.m16n8k16.row.col.f32.f16.f16.f32 " \
                 "{%0,%1,%2,%3}, {%4,%5,%6,%7}, {%8,%9}, {%0,%1,%2,%3};" \
                 : "+f"((d)[0]), "+f"((d)[1]), "+f"((d)[2]), "+f"((d)[3]) \
                 : "r"((a)[0]), "r"((a)[1]), "r"((a)[2]), "r"((a)[3]), \
                   "r"(b0v), "r"(b1v))

#define SWZ(o) ((o) ^ (((o) >> 3) & 0x70))

// Fast transcendentals: ex2/rcp/lg2 approx (rel err ~1e-7; safe vs fp16 GEMM err)
__device__ __forceinline__ float fsigm(float x) {
    float e, r;
    asm("ex2.approx.f32 %0, %1;" : "=f"(e) : "f"(-1.4426950408889634f * x));
    asm("rcp.approx.f32 %0, %1;" : "=f"(r) : "f"(1.0f + e));
    return r;
}
__device__ __forceinline__ float ftanh(float x) {
    return fmaf(2.0f, fsigm(2.0f * x), -1.0f);
}
__device__ __forceinline__ float flog2(float x) {
    float r;
    asm("lg2.approx.f32 %0, %1;" : "=f"(r) : "f"(x));
    return r;
}

// ---------------------------------------------------------------------------
// Combined prep (A pack) + W conversion — one launch, 8 elements per thread.
// Blocks [0, PREP_BLKS): pack A = fp16([input | h2_fl]); also zero g_done.
// Blocks [PREP_BLKS, ...): convert W1 then W2 to fp16.
// ---------------------------------------------------------------------------
constexpr int PREP_BLKS  = (B_ * KD) / (256 * 8);          // 4096
constexpr int WCONV_BLKS = (2 * ND * KD) / (256 * 8);      // 10240

__global__ void prep_all_kernel(const float* __restrict__ inp,
                                const int*   __restrict__ hidden,
                                const float* __restrict__ W1src,
                                const float* __restrict__ W2src)
{
    const int b = blockIdx.x;
    if (b < PREP_BLKS) {
        if (b == 0 && threadIdx.x < 32) g_done[threadIdx.x] = 0;
        const int idx = (b * 256 + threadIdx.x) * 8;
        const int i = idx >> 11;
        const int k = idx & 2047;                  // multiple of 8; no straddle
        __half h[8];
        if (k < 1024) {
            const float4 f0 = *(const float4*)(inp + (size_t)i * 1024 + k);
            const float4 f1 = *(const float4*)(inp + (size_t)i * 1024 + k + 4);
            h[0]=__float2half_rn(f0.x); h[1]=__float2half_rn(f0.y);
            h[2]=__float2half_rn(f0.z); h[3]=__float2half_rn(f0.w);
            h[4]=__float2half_rn(f1.x); h[5]=__float2half_rn(f1.y);
            h[6]=__float2half_rn(f1.z); h[7]=__float2half_rn(f1.w);
        } else {
            const int4 v0 = *(const int4*)(hidden + (size_t)i * 4096 + k);
            const int4 v1 = *(const int4*)(hidden + (size_t)i * 4096 + k + 4);
            const float s = 1.0f / 8388608.0f;
            h[0]=__float2half_rn((float)v0.x*s); h[1]=__float2half_rn((float)v0.y*s);
            h[2]=__float2half_rn((float)v0.z*s); h[3]=__float2half_rn((float)v0.w*s);
            h[4]=__float2half_rn((float)v1.x*s); h[5]=__float2half_rn((float)v1.y*s);
            h[6]=__float2half_rn((float)v1.z*s); h[7]=__float2half_rn((float)v1.w*s);
        }
        *(uint4*)(g_A + idx) = *(const uint4*)h;
    } else {
        constexpr size_t HALF = (size_t)ND * KD;
        const size_t idx = ((size_t)(b - PREP_BLKS) * 256 + threadIdx.x) * 8;
        const float* src = (idx < HALF) ? (W1src + idx) : (W2src + (idx - HALF));
        __half* dst = (idx < HALF) ? (g_W1 + idx) : (g_W2 + (idx - HALF));
        const float4 f0 = *(const float4*)(src);
        const float4 f1 = *(const float4*)(src + 4);
        __half h[8];
        h[0]=__float2half_rn(f0.x); h[1]=__float2half_rn(f0.y);
        h[2]=__float2half_rn(f0.z); h[3]=__float2half_rn(f0.w);
        h[4]=__float2half_rn(f1.x); h[5]=__float2half_rn(f1.y);
        h[6]=__float2half_rn(f1.z); h[7]=__float2half_rn(f1.w);
        *(uint4*)dst = *(const uint4*)h;
    }
}

// ---------------------------------------------------------------------------
// MERGED fused GEMM + fixed-point half-step for BOTH steps in one launch.
// bid < 1024: step 0;  bid >= 1024: step 1 (tile config = R12 best).
// CTA: M=128 x 32 j-columns x 5 gates. 8 warps: wm=(wid&1)*64, wjj=(wid>>1)*8.
// K-chunk 64, SW128, 3-stage cp.async, one barrier per chunk.
// Step-1 chunks 0-15 (input half) have no dependency -> overlap step-0 tail;
// chunk 16+ (h1 from g_Ah1) gated on g_done[bm/128]==32.
// ---------------------------------------------------------------------------
constexpr int TMM = 128;
constexpr int A_BYTES = TMM * 128;                 // 16384 per stage
constexpr int B_BYTES = 160 * 128;                 // 20480 per stage
constexpr int STAGE_BYTES = A_BYTES + B_BYTES;     // 36864
constexpr int SMEM_TOTAL = 3 * STAGE_BYTES;        // 110592
constexpr int NCHUNK = KD / 64;                    // 32

__global__ __launch_bounds__(256, 2)
void gemm_fused_kernel(const float* __restrict__ bias1,
                       const float* __restrict__ bias2,
                       const int* __restrict__ hidden,
                       float* __restrict__ out)
{
    extern __shared__ char smem[];
    __shared__ double sred[256];
    const uint32_t sb = smem_u32(smem);
    const int tid  = threadIdx.x;
    const int wid  = tid >> 5;
    const int lane = tid & 31;
    const int bid  = blockIdx.x;
    const int step = bid >> 10;                    // 0 or 1
    const int r    = bid & 1023;
    const int bj0  = (r & 31) * 32;
    const int bm   = (r >> 5) * TMM;
    const float* __restrict__ bias = step ? bias2 : bias1;
    const __half* __restrict__ Wg  = step ? g_W2 : g_W1;

    // ---- producer setup: 4 A + 5 B cp.async per thread per stage ----
    const int prow = tid >> 3;                     // 0..31
    const int pgrp = tid & 7;                      // 0..7
    const char* Abase  = (const char*)(g_A   + (size_t)(bm + prow) * KD) + pgrp * 16;
    const char* Hbase  = (const char*)(g_Ah1 + (size_t)(bm + prow) * G_) + pgrp * 16;
    const char* Bbase  = (const char*)(Wg + (size_t)(bj0 + prow) * KD) + pgrp * 16;
    const uint32_t dA = SWZ((uint32_t)(prow * 128 + pgrp * 16));   // row step 32 is SWZ-safe
    constexpr size_t ASTRIDE = (size_t)32 * KD * 2;                // +32 rows in g_A
    constexpr size_t HSTRIDE = (size_t)32 * G_ * 2;                // +32 rows in g_Ah1
    constexpr size_t BSTRIDE = (size_t)1024 * KD * 2;              // next gate
    const bool useH = (step != 0);

    // ---- consumer setup ----
    const int wm  = (wid & 1) * 64;                // warp M offset
    const int wjj = (wid >> 1) * 8;                // warp j-slice
    const int q   = lane >> 3;                     // quad
    const int l7  = lane & 7;

    uint32_t a_rt[4], a_xor[4];
#pragma unroll
    for (int mt = 0; mt < 4; mt++) {
        const int row = wm + mt * 16 + l7 + (q & 1) * 8;
        a_rt[mt]  = (uint32_t)row * 128;
        a_xor[mt] = (uint32_t)(row & 7) * 16;
    }
    const uint32_t a_kh = (uint32_t)(q >> 1) * 16;

    uint32_t b_rt[5];
#pragma unroll
    for (int gt = 0; gt < 5; gt++)
        b_rt[gt] = (uint32_t)(A_BYTES + (gt * 32 + wjj + l7) * 128);
    const uint32_t b_xor = (uint32_t)l7 * 16;
    const uint32_t b_kh  = (uint32_t)(q & 1) * 16;

    float acc[4][5][4];
#pragma unroll
    for (int mt = 0; mt < 4; mt++)
#pragma unroll
        for (int gt = 0; gt < 5; gt++)
#pragma unroll
            for (int rr = 0; rr < 4; rr++) acc[mt][gt][rr] = 0.0f;

    // ---- prologue: chunks 0,1 (input half -> g_A; no dependency) ----
#pragma unroll
    for (int s = 0; s < 2; s++) {
        const uint32_t sdst = sb + s * STAGE_BYTES;
        const size_t koff = (size_t)s * 128;
#pragma unroll
        for (int i = 0; i < 4; i++)
            cp_async16(sdst + dA + i * 4096, Abase + i * ASTRIDE + koff);
#pragma unroll
        for (int j = 0; j < 5; j++)
            cp_async16(sdst + A_BYTES + dA + j * 4096, Bbase + j * BSTRIDE + koff);
        CP_COMMIT();
    }

    // ---- main loop: one barrier per chunk ----
    int sc = 0, sl = 2;
    for (int c = 0; c < NCHUNK; c++) {
        CP_WAIT(1);
        __syncthreads();

        // Before issuing chunk 16 (first h1 chunk), step-1 waits for all 32
        // step-0 CTAs covering this m-block to have published h1.
        if (useH && c == 14) {
            if (tid == 0) {
                while (atomicAdd(&g_done[bm >> 7], 0) < 32) __nanosleep(200);
            }
            __syncthreads();
            __threadfence();
        }

        if (c + 2 < NCHUNK) {
            const uint32_t sdst = sb + sl * STAGE_BYTES;
            const int cl = c + 2;
            if (useH && cl >= 16) {                 // h half from g_Ah1
                const size_t koff = (size_t)(cl - 16) * 128;
#pragma unroll
                for (int i = 0; i < 4; i++)
                    cp_async16(sdst + dA + i * 4096, Hbase + i * HSTRIDE + koff);
            } else {                                // input half / step-0 h2 from g_A
                const size_t koff = (size_t)cl * 128;
#pragma unroll
                for (int i = 0; i < 4; i++)
                    cp_async16(sdst + dA + i * 4096, Abase + i * ASTRIDE + koff);
            }
            const size_t koffB = (size_t)cl * 128;
#pragma unroll
            for (int j = 0; j < 5; j++)
                cp_async16(sdst + A_BYTES + dA + j * 4096, Bbase + j * BSTRIDE + koffB);
        }
        CP_COMMIT();

        const uint32_t sA = sb + sc * STAGE_BYTES;
#pragma unroll
        for (int kk = 0; kk < 4; kk++) {
            const uint32_t kb = kk * 32;
            const uint32_t bko = (kb + b_kh) ^ b_xor;   // folded once per kk
            uint32_t af[4][4];
#pragma unroll
            for (int mt = 0; mt < 4; mt++)
                LDSM4(af[mt][0], af[mt][1], af[mt][2], af[mt][3],
                      sA + a_rt[mt] + ((kb + a_kh) ^ a_xor[mt]));
            uint32_t bf[5][2];
#pragma unroll
            for (int gt = 0; gt < 5; gt++)
                LDSM2(bf[gt][0], bf[gt][1], sA + b_rt[gt] + bko);
#pragma unroll
            for (int mt = 0; mt < 4; mt++)
#pragma unroll
                for (int gt = 0; gt < 5; gt++)
                    MMA16816(acc[mt][gt], af[mt], bf[gt][0], bf[gt][1]);
        }

        sc = (sc == 2) ? 0 : sc + 1;
        sl = (sl == 2) ? 0 : sl + 1;
    }

    // ---- fused elementwise epilogue (all 5 gates resident in registers) ----
    const int trow = lane >> 2;
    const int tcol = (lane & 3) * 2;
    const int jb   = bj0 + wjj + tcol;             // global j for cc=0

    float bz[5][2];
#pragma unroll
    for (int gt = 0; gt < 5; gt++) {
        bz[gt][0] = __ldg(bias + gt * 1024 + jb);
        bz[gt][1] = __ldg(bias + gt * 1024 + jb + 1);
    }

    double lsum = 0.0;
#pragma unroll
    for (int mt = 0; mt < 4; mt++) {
#pragma unroll
        for (int r2 = 0; r2 < 2; r2++) {
            const int i = bm + wm + mt * 16 + trow + r2 * 8;
            const int* hrow = hidden + (size_t)i * 4096;
            const size_t ro = (size_t)i * 4096;
            const size_t oo = OUT_OH + (size_t)i * 2048 + (size_t)step * 1024;
#pragma unroll
            for (int cc = 0; cc < 2; cc++) {
                const int j = jb + cc;
                const int a = r2 * 2 + cc;
                const float xz = acc[mt][0][a] + bz[0][cc];
                const float xg = acc[mt][1][a] + bz[1][cc];
                const float xf = acc[mt][2][a] + bz[2][cc];
                const float xo = acc[mt][3][a] + bz[3][cc];
                const float xp = acc[mt][4][a] + bz[4][cc];

                const float z  = 0.96875f * fsigm(xz) + 0.03125f;
                const float gg = ftanh(xg);
                const float f  = fsigm(xf);
                const float o  = fsigm(xo);
                const float p  = 0.96875f * fsigm(xp) + 0.03125f;

                int zi = (int)(z * 1024.0f); if (zi < 1) zi = 1;
                int pi = (int)(p * 1024.0f); if (pi < 1) pi = 1;

                const int cv = hrow[(2 + step) * 1024 + j];
                const int hv = hrow[step * 1024 + j];

                const int cn = (int)(((long long)cv * (long long)zi) >> 10)
                             + (int)(f * gg * 8388608.0f);
                const float cfl = (float)cn * (1.0f / 8388608.0f);
                const int hn = (int)(((long long)hv * (long long)pi) >> 10)
                             + (int)(o * ftanh(cfl) * 8388608.0f);

                out[ro + (size_t)step * 1024 + j]       = (float)hn;
                out[ro + (size_t)(2 + step) * 1024 + j] = (float)cn;
                const float hfl = (float)hn * (1.0f / 8388608.0f);
                out[oo + j] = hfl;
                if (step == 0)
                    g_Ah1[(size_t)i * G_ + j] = __float2half_rn(hfl);

                lsum += (double)flog2(z * p);      // sum of log2 directly
            }
        }
    }

    // Publish h1 for step 1.
    if (step == 0) __threadfence();

    // ---- deterministic per-CTA log2 reduction ----
    sred[tid] = lsum;
    __syncthreads();
#pragma unroll
    for (int s = 128; s > 0; s >>= 1) {
        if (tid < s) sred[tid] += sred[tid + s];
        __syncthreads();
    }
    if (tid == 0) {
        g_part[step * 1024 + r] = sred[0];
        if (step == 0) atomicAdd(&g_done[bm >> 7], 1);
    }
}

// ---------------------------------------------------------------------------
// Final scalar: optimal_bits = -(sum of log2). 1024 threads, double2 loads.
// ---------------------------------------------------------------------------
__global__ void bits_kernel(float* __restrict__ out, long long last_idx)
{
    __shared__ double sred[1024];
    const int tid = threadIdx.x;
    const double2 v = *(const double2*)(g_part + tid * 2);
    sred[tid] = v.x + v.y;
    __syncthreads();
#pragma unroll
    for (int k = 512; k > 0; k >>= 1) {
        if (tid < k) sred[tid] += sred[tid + k];
        __syncthreads();
    }
    if (tid == 0)
        out[last_idx] = (float)(-sred[0]);
}

// ---------------------------------------------------------------------------
extern "C" void kernel_launch(void* const* d_in, const int* in_sizes, int n_in,
                              void* d_out, int out_size)
{
    const float* inp    = (const float*)d_in[0];   // (4096, 1024)
    const int*   hidden = (const int*)  d_in[1];   // (4096, 4096)
    const float* W1     = (const float*)d_in[2];   // (5120, 2048)
    const float* b1     = (const float*)d_in[3];
    const float* W2     = (const float*)d_in[4];
    const float* b2     = (const float*)d_in[5];
    float* out = (float*)d_out;

    static bool attr_set = false;
    if (!attr_set) {
        cudaFuncSetAttribute(gemm_fused_kernel,
                             cudaFuncAttributeMaxDynamicSharedMemorySize, SMEM_TOTAL);
        attr_set = true;
    }

    prep_all_kernel<<<PREP_BLKS + WCONV_BLKS, 256>>>(inp, hidden, W1, W2);
    gemm_fused_kernel<<<2048, 256, SMEM_TOTAL>>>(b1, b2, hidden, out);
    bits_kernel<<<1, 1024>>>(out, (long long)out_size - 1);
}